// round 10
// baseline (speedup 1.0000x reference)
#include <cuda_runtime.h>
#include <cuda_fp16.h>
#include <cstdint>

#define DM 2048   // D_MODEL
#define DF 8192   // D_FF
#define RK 32     // RANK
#define SL 512    // S

// ---------------------------------------------------------------------------
// Global scratch
// ---------------------------------------------------------------------------
__device__ __half g_Wg[DF * DM];      // gate_eff fp16
__device__ __half g_Wu[DF * DM];      // up_eff fp16
__device__ __half g_Wd[DM * DF];      // down_eff fp16
__device__ __half g_xT[SL * DM];      // x transposed [s][c] fp16
__device__ __half g_mlpT[SL * DF];    // silu(g)*u transposed [s][ff] fp16
__device__ float  g_part[4 * DM * SL];// split-K=4 partials (fp32)

// ---------------------------------------------------------------------------
// Helpers
// ---------------------------------------------------------------------------
__device__ __forceinline__ float to_tf32(float x) {
    uint32_t u;
    asm("cvt.rna.tf32.f32 %0, %1;" : "=r"(u) : "f"(x));
    return __uint_as_float(u);
}
__device__ __forceinline__ uint32_t smem_u32(const void* p) {
    uint32_t a;
    asm("{ .reg .u64 t; cvta.to.shared.u64 t, %1; cvt.u32.u64 %0, t; }" : "=r"(a) : "l"(p));
    return a;
}
__device__ __forceinline__ void cp16(uint32_t dst, const void* src) {
    asm volatile("cp.async.cg.shared.global [%0], [%1], 16;" :: "r"(dst), "l"(src));
}
__device__ __forceinline__ void cp_commit() { asm volatile("cp.async.commit_group;"); }
__device__ __forceinline__ void cp_wait1()  { asm volatile("cp.async.wait_group 1;" ::: "memory"); }
__device__ __forceinline__ void cp_wait0()  { asm volatile("cp.async.wait_group 0;" ::: "memory"); }

// tf32 m16n8k8 (dequant scale GEMM)
__device__ __forceinline__ void mma8(float* c, const float* a, const float* b) {
    asm volatile(
        "mma.sync.aligned.m16n8k8.row.col.f32.tf32.tf32.f32 "
        "{%0,%1,%2,%3}, {%4,%5,%6,%7}, {%8,%9}, {%0,%1,%2,%3};"
        : "+f"(c[0]), "+f"(c[1]), "+f"(c[2]), "+f"(c[3])
        : "r"(__float_as_uint(a[0])), "r"(__float_as_uint(a[1])),
          "r"(__float_as_uint(a[2])), "r"(__float_as_uint(a[3])),
          "r"(__float_as_uint(b[0])), "r"(__float_as_uint(b[1])));
}
// fp16 m16n8k16 (main GEMMs), fp32 accum
__device__ __forceinline__ void mma16(float* c, const uint32_t* a, const uint32_t* b) {
    asm volatile(
        "mma.sync.aligned.m16n8k16.row.col.f32.f16.f16.f32 "
        "{%0,%1,%2,%3}, {%4,%5,%6,%7}, {%8,%9}, {%0,%1,%2,%3};"
        : "+f"(c[0]), "+f"(c[1]), "+f"(c[2]), "+f"(c[3])
        : "r"(a[0]), "r"(a[1]), "r"(a[2]), "r"(a[3]), "r"(b[0]), "r"(b[1]));
}
__device__ __forceinline__ void ldsm4(uint32_t* r, uint32_t addr) {
    asm volatile("ldmatrix.sync.aligned.m8n8.x4.shared.b16 {%0,%1,%2,%3}, [%4];"
                 : "=r"(r[0]), "=r"(r[1]), "=r"(r[2]), "=r"(r[3]) : "r"(addr));
}

// BK=32 tile: 128 rows x 32 k-halves padded to 40 (row stride 80 B; rows 0..7 hit
// byte-groups 0,80,32,112,64,16,96,48 mod 128 -> all distinct: ldmatrix conflict-free)
#define PADH 40
#define TILE_H (128 * PADH * 2)    // 10240 B

// ---------------------------------------------------------------------------
// Kernel 1: merged dequant for all 3 matrices (z selects matrix)
// ---------------------------------------------------------------------------
#define DQ_SMEM 67584

__global__ __launch_bounds__(256, 1) void k_dequant(
    const float* __restrict__ Gs, const float* __restrict__ GA, const float* __restrict__ GB,
    const float* __restrict__ Us, const float* __restrict__ UA, const float* __restrict__ UB,
    const float* __restrict__ Ds, const float* __restrict__ DA, const float* __restrict__ DB)
{
    extern __shared__ float dsm[];
    float* sA = dsm;                    // [128][36]
    float* sB = dsm + 128 * 36;         // [128][36] (B transposed)
    int tid = threadIdx.x, wid = tid >> 5, lane = tid & 31;
    int g = lane >> 2, tg = lane & 3;
    int wm = wid & 3, wn = wid >> 2;

    const float *Ws, *Aa, *Bb;
    __half* Wo;
    int cols, cb, fb;
    if (blockIdx.z == 0) {
        Ws = Gs; Aa = GA; Bb = GB; Wo = g_Wg; cols = DM;
        cb = (blockIdx.x & 15) * 128; fb = (blockIdx.x >> 4) * 128;
    } else if (blockIdx.z == 1) {
        Ws = Us; Aa = UA; Bb = UB; Wo = g_Wu; cols = DM;
        cb = (blockIdx.x & 15) * 128; fb = (blockIdx.x >> 4) * 128;
    } else {
        Ws = Ds; Aa = DA; Bb = DB; Wo = g_Wd; cols = DF;
        cb = (blockIdx.x & 63) * 128; fb = (blockIdx.x >> 6) * 128;
    }

    #pragma unroll
    for (int t = 0; t < 16; t++) {
        int idx = tid + t * 256;
        int r = idx >> 5, k = idx & 31;
        sA[r * 36 + k] = to_tf32(Aa[(fb + r) * RK + k]);
        int rr = idx >> 7, c = idx & 127;
        sB[c * 36 + rr] = to_tf32(Bb[rr * cols + cb + c]);
    }
    __syncthreads();

    float acc[2][8][4];
    #pragma unroll
    for (int mt = 0; mt < 2; mt++)
        #pragma unroll
        for (int nt = 0; nt < 8; nt++)
            #pragma unroll
            for (int i = 0; i < 4; i++) acc[mt][nt][i] = 0.f;

    #pragma unroll
    for (int ks = 0; ks < 4; ks++) {
        int k0 = ks * 8;
        float bq[8][2];
        #pragma unroll
        for (int nt = 0; nt < 8; nt++) {
            const float* bp = sB + (wn * 64 + nt * 8 + g) * 36 + k0 + tg;
            bq[nt][0] = bp[0]; bq[nt][1] = bp[4];
        }
        #pragma unroll
        for (int mt = 0; mt < 2; mt++) {
            const float* ap = sA + (wm * 32 + mt * 16 + g) * 36 + k0 + tg;
            float a[4] = { ap[0], ap[8 * 36], ap[4], ap[8 * 36 + 4] };
            #pragma unroll
            for (int nt = 0; nt < 8; nt++) mma8(acc[mt][nt], a, bq[nt]);
        }
    }
    __syncthreads();

    float* sS = dsm;   // [128][132]
    #pragma unroll
    for (int mt = 0; mt < 2; mt++)
        #pragma unroll
        for (int nt = 0; nt < 8; nt++) {
            int r0 = wm * 32 + mt * 16 + g;
            int c0 = wn * 64 + nt * 8 + 2 * tg;
            #pragma unroll
            for (int i = 0; i < 4; i++)
                sS[(r0 + (i >> 1) * 8) * 132 + c0 + (i & 1)] = acc[mt][nt][i];
        }
    __syncthreads();

    #pragma unroll
    for (int t = 0; t < 16; t++) {
        int idx = tid + t * 256;
        int r = idx >> 5, c4 = idx & 31;
        const float4 w = *(const float4*)&Ws[(fb + r) * cols + cb + c4 * 4];
        const float4 s = *(const float4*)&sS[r * 132 + c4 * 4];
        __half2 lo = __floats2half2_rn(w.x * s.x, w.y * s.y);
        __half2 hi = __floats2half2_rn(w.z * s.z, w.w * s.w);
        uint2 o = { *(uint32_t*)&lo, *(uint32_t*)&hi };
        *(uint2*)&Wo[(fb + r) * cols + cb + c4 * 4] = o;
    }
}

// ---------------------------------------------------------------------------
// x transpose -> fp16
// ---------------------------------------------------------------------------
__global__ __launch_bounds__(256, 4) void k_xt(const float* __restrict__ x)
{
    __shared__ float sm[32][33];
    int tid = threadIdx.x, tx = tid & 31, ty = tid >> 5;
    int cb = blockIdx.x * 32, sb = blockIdx.y * 32;
    #pragma unroll
    for (int i = 0; i < 4; i++)
        sm[ty + i * 8][tx] = x[(cb + ty + i * 8) * SL + sb + tx];
    __syncthreads();
    #pragma unroll
    for (int i = 0; i < 4; i++)
        g_xT[(sb + ty + i * 8) * DM + cb + tx] = __float2half_rn(sm[tx][ty + i * 8]);
}

// ---------------------------------------------------------------------------
// Stage loader: 128 rows x 32 k-halves -> [row][PADH]; 2 cp16 per thread
// ---------------------------------------------------------------------------
__device__ __forceinline__ void load_tile32(uint32_t dst, const __half* __restrict__ src,
                                            int row_base, int ld, int c0, int tid)
{
    #pragma unroll
    for (int t = 0; t < 2; t++) {
        int id = tid + t * 256;         // 0..511
        int r = id >> 2, cbk = id & 3;
        cp16(dst + (r * PADH + cbk * 8) * 2, src + (row_base + r) * ld + c0 + cbk * 8);
    }
}

// ldmatrix per-lane byte offsets (PADH*2 = 80 B row stride)
__device__ __forceinline__ uint32_t a_off(int lane, int row_base) {
    return (uint32_t)((row_base + (lane & 15)) * (PADH * 2) + ((lane >> 4) * 16));
}
__device__ __forceinline__ uint32_t b_off(int lane, int row_base) {
    return (uint32_t)((row_base + ((lane >> 4) * 8) + (lane & 7)) * (PADH * 2) +
                      (((lane >> 3) & 1) * 16));
}
#define ROW16 (16 * PADH * 2)   // 1280 B per 16-row step

// ---------------------------------------------------------------------------
// Kernel 2: gate+up fp16 GEMM + SwiGLU -> g_mlpT (fp16)
// CTA: 128 f x 128 s, BK=32, 64 iters, 3-stage pipeline, 1 sync/iter.
// SMEM: 3 x (Ag|Au|Bx = 30720 B) = 92160 B -> 2 CTAs/SM (16 warps).
// ---------------------------------------------------------------------------
#define K2_STG (3 * TILE_H)
#define K2_SMEM (3 * K2_STG)

__global__ __launch_bounds__(256, 2) void k_gemm_gateup()
{
    extern __shared__ char smemc[];
    __half* smh = (__half*)smemc;
    const uint32_t su = smem_u32(smemc);
    const int tid = threadIdx.x, wid = tid >> 5, lane = tid & 31;
    const int g = lane >> 2, tg = lane & 3;
    const int warp_m = wid & 3, warp_n = wid >> 2;
    const int sb = blockIdx.x * 128, fbase = blockIdx.y * 128;

    const uint32_t rA = a_off(lane, warp_m * 32);
    const uint32_t rB = b_off(lane, warp_n * 64);

    float accg[2][8][4], accu[2][8][4];
    #pragma unroll
    for (int mt = 0; mt < 2; mt++)
        #pragma unroll
        for (int nt = 0; nt < 8; nt++)
            #pragma unroll
            for (int i = 0; i < 4; i++) { accg[mt][nt][i] = 0.f; accu[mt][nt][i] = 0.f; }

    #pragma unroll
    for (int p = 0; p < 2; p++) {
        uint32_t b = su + p * K2_STG;
        load_tile32(b,              g_Wg, fbase, DM, p * 32, tid);
        load_tile32(b + TILE_H,     g_Wu, fbase, DM, p * 32, tid);
        load_tile32(b + 2 * TILE_H, g_xT, sb,    DM, p * 32, tid);
        cp_commit();
    }

    int stg = 0;
    for (int i = 0; i < 64; i++) {
        if (i == 63) cp_wait0(); else cp_wait1();
        __syncthreads();
        if (i < 62) {
            int ns = stg + 2; if (ns >= 3) ns -= 3;
            uint32_t b = su + ns * K2_STG;
            int c0 = (i + 2) * 32;
            load_tile32(b,              g_Wg, fbase, DM, c0, tid);
            load_tile32(b + TILE_H,     g_Wu, fbase, DM, c0, tid);
            load_tile32(b + 2 * TILE_H, g_xT, sb,    DM, c0, tid);
            cp_commit();
        }

        const uint32_t bAg = su + stg * K2_STG;
        const uint32_t bAu = bAg + TILE_H;
        const uint32_t bBx = bAg + 2 * TILE_H;

        #pragma unroll
        for (int ks = 0; ks < 2; ks++) {
            const uint32_t kb = ks * 32;   // 16 halves = 32 B
            uint32_t bq[4][4];
            #pragma unroll
            for (int p = 0; p < 4; p++)
                ldsm4(bq[p], bBx + rB + p * ROW16 + kb);
            #pragma unroll
            for (int mt = 0; mt < 2; mt++) {
                uint32_t ag[4], au[4];
                ldsm4(ag, bAg + rA + mt * ROW16 + kb);
                ldsm4(au, bAu + rA + mt * ROW16 + kb);
                #pragma unroll
                for (int p = 0; p < 4; p++) {
                    mma16(accg[mt][2 * p],     ag, &bq[p][0]);
                    mma16(accg[mt][2 * p + 1], ag, &bq[p][2]);
                    mma16(accu[mt][2 * p],     au, &bq[p][0]);
                    mma16(accu[mt][2 * p + 1], au, &bq[p][2]);
                }
            }
        }
        if (++stg == 3) stg = 0;
    }
    __syncthreads();

    // epilogue: SwiGLU, transpose via smem, coalesced write
    __half* so = smh;   // [s 128][f pad 136] halves = 34816 B
    #pragma unroll
    for (int mt = 0; mt < 2; mt++)
        #pragma unroll
        for (int nt = 0; nt < 8; nt++) {
            int r0 = warp_m * 32 + mt * 16 + g;
            int c0 = warp_n * 64 + nt * 8 + 2 * tg;
            #pragma unroll
            for (int i = 0; i < 4; i++) {
                float gg = accg[mt][nt][i], uu = accu[mt][nt][i];
                float m = (gg / (1.f + __expf(-gg))) * uu;
                so[(c0 + (i & 1)) * 136 + r0 + (i >> 1) * 8] = __float2half_rn(m);
            }
        }
    __syncthreads();
    #pragma unroll
    for (int t = 0; t < 32; t++) {
        int idx = tid + t * 256;
        int s = idx >> 6, f2 = idx & 63;
        uint32_t v = *(const uint32_t*)&so[s * 136 + f2 * 2];
        *(uint32_t*)&g_mlpT[(sb + s) * DF + fbase + f2 * 2] = v;
    }
}

// ---------------------------------------------------------------------------
// Kernel 3: down fp16 GEMM, split-K=4 -> g_part.  CTA: 128 m x 128 s, BK=32.
// grid (4, 16, 4) = 256 CTAs, 2 CTAs/SM -> single wave.
// SMEM: 3 x (Ad|Bm = 20480 B) = 61440; epilogue needs 67584 -> K3_SMEM.
// ---------------------------------------------------------------------------
#define K3_STG (2 * TILE_H)
#define K3_SMEM 67584

__global__ __launch_bounds__(256, 2) void k_gemm_down()
{
    extern __shared__ char smemc[];
    const uint32_t su = smem_u32(smemc);
    const int tid = threadIdx.x, wid = tid >> 5, lane = tid & 31;
    const int g = lane >> 2, tg = lane & 3;
    const int warp_m = wid & 3, warp_n = wid >> 2;
    const int sb = blockIdx.x * 128, mbase = blockIdx.y * 128;
    const int kbase = blockIdx.z * 2048;

    const uint32_t rA = a_off(lane, warp_m * 32);
    const uint32_t rB = b_off(lane, warp_n * 64);

    float acc[2][8][4];
    #pragma unroll
    for (int mt = 0; mt < 2; mt++)
        #pragma unroll
        for (int nt = 0; nt < 8; nt++)
            #pragma unroll
            for (int i = 0; i < 4; i++) acc[mt][nt][i] = 0.f;

    #pragma unroll
    for (int p = 0; p < 2; p++) {
        uint32_t b = su + p * K3_STG;
        load_tile32(b,          g_Wd,   mbase, DF, kbase + p * 32, tid);
        load_tile32(b + TILE_H, g_mlpT, sb,    DF, kbase + p * 32, tid);
        cp_commit();
    }

    int stg = 0;
    for (int i = 0; i < 64; i++) {
        if (i == 63) cp_wait0(); else cp_wait1();
        __syncthreads();
        if (i < 62) {
            int ns = stg + 2; if (ns >= 3) ns -= 3;
            uint32_t b = su + ns * K3_STG;
            int c0 = kbase + (i + 2) * 32;
            load_tile32(b,          g_Wd,   mbase, DF, c0, tid);
            load_tile32(b + TILE_H, g_mlpT, sb,    DF, c0, tid);
            cp_commit();
        }

        const uint32_t bAd = su + stg * K3_STG;
        const uint32_t bBm = bAd + TILE_H;

        #pragma unroll
        for (int ks = 0; ks < 2; ks++) {
            const uint32_t kb = ks * 32;
            uint32_t bq[4][4];
            #pragma unroll
            for (int p = 0; p < 4; p++)
                ldsm4(bq[p], bBm + rB + p * ROW16 + kb);
            #pragma unroll
            for (int mt = 0; mt < 2; mt++) {
                uint32_t a[4];
                ldsm4(a, bAd + rA + mt * ROW16 + kb);
                #pragma unroll
                for (int p = 0; p < 4; p++) {
                    mma16(acc[mt][2 * p],     a, &bq[p][0]);
                    mma16(acc[mt][2 * p + 1], a, &bq[p][2]);
                }
            }
        }
        if (++stg == 3) stg = 0;
    }
    __syncthreads();

    // epilogue: stage [m][s] fp32, coalesced float4 partial writes
    float* so = (float*)smemc;   // [128][132] = 67584 B
    #pragma unroll
    for (int mt = 0; mt < 2; mt++)
        #pragma unroll
        for (int nt = 0; nt < 8; nt++) {
            int r0 = warp_m * 32 + mt * 16 + g;
            int c0 = warp_n * 64 + nt * 8 + 2 * tg;
            #pragma unroll
            for (int i = 0; i < 4; i++)
                so[(r0 + (i >> 1) * 8) * 132 + c0 + (i & 1)] = acc[mt][nt][i];
        }
    __syncthreads();
    #pragma unroll
    for (int t = 0; t < 16; t++) {
        int idx = tid + t * 256;
        int m = idx >> 5, c4 = idx & 31;
        float4 v = *(const float4*)&so[m * 132 + c4 * 4];
        *(float4*)&g_part[(blockIdx.z * DM + mbase + m) * SL + sb + c4 * 4] = v;
    }
}

// ---------------------------------------------------------------------------
// Kernel 4: split-K reduce (K=4)
// ---------------------------------------------------------------------------
__global__ __launch_bounds__(256, 4) void k_reduce(float* __restrict__ out)
{
    int i = blockIdx.x * 256 + threadIdx.x;
    const float4* p = (const float4*)g_part;
    const int n4 = DM * SL / 4;
    float4 a = p[i], b = p[i + n4], c = p[i + 2 * n4], d = p[i + 3 * n4];
    float4 o;
    o.x = a.x + b.x + c.x + d.x;
    o.y = a.y + b.y + c.y + d.y;
    o.z = a.z + b.z + c.z + d.z;
    o.w = a.w + b.w + c.w + d.w;
    ((float4*)out)[i] = o;
}

// ---------------------------------------------------------------------------
extern "C" void kernel_launch(void* const* d_in, const int* in_sizes, int n_in,
                              void* d_out, int out_size)
{
    (void)in_sizes; (void)n_in; (void)out_size;
    const float* x  = (const float*)d_in[0];
    const float* Gs = (const float*)d_in[1];
    const float* GA = (const float*)d_in[2];
    const float* GB = (const float*)d_in[3];
    const float* Us = (const float*)d_in[4];
    const float* UA = (const float*)d_in[5];
    const float* UB = (const float*)d_in[6];
    const float* Ds = (const float*)d_in[7];
    const float* DA = (const float*)d_in[8];
    const float* DB = (const float*)d_in[9];
    float* out = (float*)d_out;

    cudaFuncSetAttribute(k_dequant,     cudaFuncAttributeMaxDynamicSharedMemorySize, DQ_SMEM);
    cudaFuncSetAttribute(k_gemm_gateup, cudaFuncAttributeMaxDynamicSharedMemorySize, K2_SMEM);
    cudaFuncSetAttribute(k_gemm_down,   cudaFuncAttributeMaxDynamicSharedMemorySize, K3_SMEM);

    k_dequant<<<dim3(1024, 1, 3), 256, DQ_SMEM>>>(Gs, GA, GB, Us, UA, UB, Ds, DA, DB);
    k_xt<<<dim3(DM / 32, SL / 32), 256>>>(x);

    k_gemm_gateup<<<dim3(SL / 128, DF / 128), 256, K2_SMEM>>>();
    k_gemm_down<<<dim3(SL / 128, DM / 128, 4), 256, K3_SMEM>>>();
    k_reduce<<<DM * SL / 4 / 256, 256>>>(out);
}

// round 11
// speedup vs baseline: 1.7147x; 1.7147x over previous
#include <cuda_runtime.h>
#include <cuda_fp16.h>
#include <cstdint>

#define DM 2048   // D_MODEL
#define DF 8192   // D_FF
#define RK 32     // RANK
#define SL 512    // S

// ---------------------------------------------------------------------------
// Global scratch
// ---------------------------------------------------------------------------
__device__ __half g_Wg[DF * DM];      // gate_eff fp16
__device__ __half g_Wu[DF * DM];      // up_eff fp16
__device__ __half g_Wd[DM * DF];      // down_eff fp16
__device__ __half g_xT[SL * DM];      // x transposed [s][c] fp16
__device__ __half g_mlpT[SL * DF];    // silu(g)*u transposed [s][ff] fp16
__device__ float  g_part[2 * DM * SL];// split-K=2 partials (fp32)

// ---------------------------------------------------------------------------
// Helpers
// ---------------------------------------------------------------------------
__device__ __forceinline__ float to_tf32(float x) {
    uint32_t u;
    asm("cvt.rna.tf32.f32 %0, %1;" : "=r"(u) : "f"(x));
    return __uint_as_float(u);
}
__device__ __forceinline__ uint32_t smem_u32(const void* p) {
    uint32_t a;
    asm("{ .reg .u64 t; cvta.to.shared.u64 t, %1; cvt.u32.u64 %0, t; }" : "=r"(a) : "l"(p));
    return a;
}
__device__ __forceinline__ void cp16(uint32_t dst, const void* src) {
    asm volatile("cp.async.cg.shared.global [%0], [%1], 16;" :: "r"(dst), "l"(src));
}
__device__ __forceinline__ void cp_commit() { asm volatile("cp.async.commit_group;"); }
__device__ __forceinline__ void cp_wait1()  { asm volatile("cp.async.wait_group 1;" ::: "memory"); }
__device__ __forceinline__ void cp_wait0()  { asm volatile("cp.async.wait_group 0;" ::: "memory"); }

// tf32 m16n8k8 (dequant scale GEMM)
__device__ __forceinline__ void mma8(float* c, const float* a, const float* b) {
    asm volatile(
        "mma.sync.aligned.m16n8k8.row.col.f32.tf32.tf32.f32 "
        "{%0,%1,%2,%3}, {%4,%5,%6,%7}, {%8,%9}, {%0,%1,%2,%3};"
        : "+f"(c[0]), "+f"(c[1]), "+f"(c[2]), "+f"(c[3])
        : "r"(__float_as_uint(a[0])), "r"(__float_as_uint(a[1])),
          "r"(__float_as_uint(a[2])), "r"(__float_as_uint(a[3])),
          "r"(__float_as_uint(b[0])), "r"(__float_as_uint(b[1])));
}
// fp16 m16n8k16 (main GEMMs), fp32 accum
__device__ __forceinline__ void mma16(float* c, const uint32_t* a, const uint32_t* b) {
    asm volatile(
        "mma.sync.aligned.m16n8k16.row.col.f32.f16.f16.f32 "
        "{%0,%1,%2,%3}, {%4,%5,%6,%7}, {%8,%9}, {%0,%1,%2,%3};"
        : "+f"(c[0]), "+f"(c[1]), "+f"(c[2]), "+f"(c[3])
        : "r"(a[0]), "r"(a[1]), "r"(a[2]), "r"(a[3]), "r"(b[0]), "r"(b[1]));
}
__device__ __forceinline__ void ldsm4(uint32_t* r, uint32_t addr) {
    asm volatile("ldmatrix.sync.aligned.m8n8.x4.shared.b16 {%0,%1,%2,%3}, [%4];"
                 : "=r"(r[0]), "=r"(r[1]), "=r"(r[2]), "=r"(r[3]) : "r"(addr));
}

// BK=64 tile: 128 rows x 64 k-halves padded to 72 (row stride 144 B, conflict-free ldmatrix)
#define PADH 72
#define TILE_H (128 * PADH * 2)    // 18432 B

// ---------------------------------------------------------------------------
// Kernel 1: merged dequant for all 3 matrices, fragment-direct epilogue.
// smem: only sA|sB (36864 B) -> multiple CTAs/SM; memory-bound.
// ---------------------------------------------------------------------------
__global__ __launch_bounds__(256) void k_dequant(
    const float* __restrict__ Gs, const float* __restrict__ GA, const float* __restrict__ GB,
    const float* __restrict__ Us, const float* __restrict__ UA, const float* __restrict__ UB,
    const float* __restrict__ Ds, const float* __restrict__ DA, const float* __restrict__ DB)
{
    __shared__ float sA[128 * 36];      // [f][36]
    __shared__ float sB[128 * 36];      // [c][36] (B transposed)
    int tid = threadIdx.x, wid = tid >> 5, lane = tid & 31;
    int g = lane >> 2, tg = lane & 3;
    int wm = wid & 3, wn = wid >> 2;

    const float *Ws, *Aa, *Bb;
    __half* Wo;
    int cols, cb, fb;
    if (blockIdx.z == 0) {
        Ws = Gs; Aa = GA; Bb = GB; Wo = g_Wg; cols = DM;
        cb = (blockIdx.x & 15) * 128; fb = (blockIdx.x >> 4) * 128;
    } else if (blockIdx.z == 1) {
        Ws = Us; Aa = UA; Bb = UB; Wo = g_Wu; cols = DM;
        cb = (blockIdx.x & 15) * 128; fb = (blockIdx.x >> 4) * 128;
    } else {
        Ws = Ds; Aa = DA; Bb = DB; Wo = g_Wd; cols = DF;
        cb = (blockIdx.x & 63) * 128; fb = (blockIdx.x >> 6) * 128;
    }

    #pragma unroll
    for (int t = 0; t < 16; t++) {
        int idx = tid + t * 256;
        int r = idx >> 5, k = idx & 31;
        sA[r * 36 + k] = to_tf32(Aa[(fb + r) * RK + k]);
        int rr = idx >> 7, c = idx & 127;
        sB[c * 36 + rr] = to_tf32(Bb[rr * cols + cb + c]);
    }
    __syncthreads();

    float acc[2][8][4];
    #pragma unroll
    for (int mt = 0; mt < 2; mt++)
        #pragma unroll
        for (int nt = 0; nt < 8; nt++)
            #pragma unroll
            for (int i = 0; i < 4; i++) acc[mt][nt][i] = 0.f;

    #pragma unroll
    for (int ks = 0; ks < 4; ks++) {
        int k0 = ks * 8;
        float bq[8][2];
        #pragma unroll
        for (int nt = 0; nt < 8; nt++) {
            const float* bp = sB + (wn * 64 + nt * 8 + g) * 36 + k0 + tg;
            bq[nt][0] = bp[0]; bq[nt][1] = bp[4];
        }
        #pragma unroll
        for (int mt = 0; mt < 2; mt++) {
            const float* ap = sA + (wm * 32 + mt * 16 + g) * 36 + k0 + tg;
            float a[4] = { ap[0], ap[8 * 36], ap[4], ap[8 * 36 + 4] };
            #pragma unroll
            for (int nt = 0; nt < 8; nt++) mma8(acc[mt][nt], a, bq[nt]);
        }
    }

    // Fragment-direct epilogue: thread owns rows {r0, r0+8}, cols {c0, c0+1}.
    // Warp-level: per (mt,nt,row-half) the 4 tg-lanes read 8 consecutive floats
    // (32 B sector) and write 8 consecutive halves (16 B; L2 merges adjacent nt).
    #pragma unroll
    for (int mt = 0; mt < 2; mt++) {
        int r0 = fb + wm * 32 + mt * 16 + g;
        #pragma unroll
        for (int nt = 0; nt < 8; nt++) {
            int c0 = cb + wn * 64 + nt * 8 + 2 * tg;
            #pragma unroll
            for (int h = 0; h < 2; h++) {          // row half: +0 / +8
                int r = r0 + h * 8;
                const float2 w = *(const float2*)&Ws[r * cols + c0];
                __half2 o = __floats2half2_rn(w.x * acc[mt][nt][2 * h],
                                              w.y * acc[mt][nt][2 * h + 1]);
                *(__half2*)&Wo[r * cols + c0] = o;
            }
        }
    }
}

// ---------------------------------------------------------------------------
// x transpose -> fp16
// ---------------------------------------------------------------------------
__global__ __launch_bounds__(256, 4) void k_xt(const float* __restrict__ x)
{
    __shared__ float sm[32][33];
    int tid = threadIdx.x, tx = tid & 31, ty = tid >> 5;
    int cb = blockIdx.x * 32, sb = blockIdx.y * 32;
    #pragma unroll
    for (int i = 0; i < 4; i++)
        sm[ty + i * 8][tx] = x[(cb + ty + i * 8) * SL + sb + tx];
    __syncthreads();
    #pragma unroll
    for (int i = 0; i < 4; i++)
        g_xT[(sb + ty + i * 8) * DM + cb + tx] = __float2half_rn(sm[tx][ty + i * 8]);
}

// ---------------------------------------------------------------------------
// Stage loader: 128 rows x 64 k-halves -> [row][PADH]; 4 cp16 per thread
// ---------------------------------------------------------------------------
__device__ __forceinline__ void load_tile64(uint32_t dst, const __half* __restrict__ src,
                                            int row_base, int ld, int c0, int tid)
{
    #pragma unroll
    for (int t = 0; t < 4; t++) {
        int id = tid + t * 256;
        int r = id >> 3, cbk = id & 7;
        cp16(dst + (r * PADH + cbk * 8) * 2, src + (row_base + r) * ld + c0 + cbk * 8);
    }
}

// ldmatrix per-lane byte offsets
__device__ __forceinline__ uint32_t a_off(int lane, int row_base) {
    return (uint32_t)((row_base + (lane & 15)) * (PADH * 2) + ((lane >> 4) * 16));
}
__device__ __forceinline__ uint32_t b_off(int lane, int row_base) {
    return (uint32_t)((row_base + ((lane >> 4) * 8) + (lane & 7)) * (PADH * 2) +
                      (((lane >> 3) & 1) * 16));
}

// ---------------------------------------------------------------------------
// Kernel 2: gate+up fp16 GEMM + SwiGLU -> g_mlpT (fp16)
// CTA: 128 f x 128 s, BK=64, 32 iters, 3-stage pipeline, 1 sync/iter. (R9 config)
// SMEM: 3 stages x (Ag|Au|Bx = 55296 B) = 165888 B.
// ---------------------------------------------------------------------------
#define K2_STG (3 * TILE_H)
#define K2_SMEM (3 * K2_STG)

__global__ __launch_bounds__(256, 1) void k_gemm_gateup()
{
    extern __shared__ char smemc[];
    __half* smh = (__half*)smemc;
    const uint32_t su = smem_u32(smemc);
    const int tid = threadIdx.x, wid = tid >> 5, lane = tid & 31;
    const int g = lane >> 2, tg = lane & 3;
    const int warp_m = wid & 3, warp_n = wid >> 2;
    const int sb = blockIdx.x * 128, fbase = blockIdx.y * 128;

    const uint32_t rA = a_off(lane, warp_m * 32);
    const uint32_t rB = b_off(lane, warp_n * 64);

    float accg[2][8][4], accu[2][8][4];
    #pragma unroll
    for (int mt = 0; mt < 2; mt++)
        #pragma unroll
        for (int nt = 0; nt < 8; nt++)
            #pragma unroll
            for (int i = 0; i < 4; i++) { accg[mt][nt][i] = 0.f; accu[mt][nt][i] = 0.f; }

    #pragma unroll
    for (int p = 0; p < 2; p++) {
        uint32_t b = su + p * K2_STG;
        load_tile64(b,              g_Wg, fbase, DM, p * 64, tid);
        load_tile64(b + TILE_H,     g_Wu, fbase, DM, p * 64, tid);
        load_tile64(b + 2 * TILE_H, g_xT, sb,    DM, p * 64, tid);
        cp_commit();
    }

    int stg = 0;
    for (int i = 0; i < 32; i++) {
        if (i == 31) cp_wait0(); else cp_wait1();
        __syncthreads();
        if (i < 30) {
            int ns = stg + 2; if (ns >= 3) ns -= 3;
            uint32_t b = su + ns * K2_STG;
            int c0 = (i + 2) * 64;
            load_tile64(b,              g_Wg, fbase, DM, c0, tid);
            load_tile64(b + TILE_H,     g_Wu, fbase, DM, c0, tid);
            load_tile64(b + 2 * TILE_H, g_xT, sb,    DM, c0, tid);
            cp_commit();
        }

        const uint32_t bAg = su + stg * K2_STG;
        const uint32_t bAu = bAg + TILE_H;
        const uint32_t bBx = bAg + 2 * TILE_H;

        #pragma unroll
        for (int ks = 0; ks < 4; ks++) {
            const uint32_t kb = ks * 32;
            uint32_t bq[4][4];
            #pragma unroll
            for (int p = 0; p < 4; p++)
                ldsm4(bq[p], bBx + rB + p * 2304 + kb);
            #pragma unroll
            for (int mt = 0; mt < 2; mt++) {
                uint32_t ag[4], au[4];
                ldsm4(ag, bAg + rA + mt * 2304 + kb);
                ldsm4(au, bAu + rA + mt * 2304 + kb);
                #pragma unroll
                for (int p = 0; p < 4; p++) {
                    mma16(accg[mt][2 * p],     ag, &bq[p][0]);
                    mma16(accg[mt][2 * p + 1], ag, &bq[p][2]);
                    mma16(accu[mt][2 * p],     au, &bq[p][0]);
                    mma16(accu[mt][2 * p + 1], au, &bq[p][2]);
                }
            }
        }
        if (++stg == 3) stg = 0;
    }
    __syncthreads();

    // epilogue: SwiGLU, transpose via smem (half), coalesced write
    __half* so = smh;   // [s 128][f pad 136] halves = 34816 B
    #pragma unroll
    for (int mt = 0; mt < 2; mt++)
        #pragma unroll
        for (int nt = 0; nt < 8; nt++) {
            int r0 = warp_m * 32 + mt * 16 + g;
            int c0 = warp_n * 64 + nt * 8 + 2 * tg;
            #pragma unroll
            for (int i = 0; i < 4; i++) {
                float gg = accg[mt][nt][i], uu = accu[mt][nt][i];
                float m = (gg / (1.f + __expf(-gg))) * uu;
                so[(c0 + (i & 1)) * 136 + r0 + (i >> 1) * 8] = __float2half_rn(m);
            }
        }
    __syncthreads();
    #pragma unroll
    for (int t = 0; t < 32; t++) {
        int idx = tid + t * 256;
        int s = idx >> 6, f2 = idx & 63;
        uint32_t v = *(const uint32_t*)&so[s * 136 + f2 * 2];
        *(uint32_t*)&g_mlpT[(sb + s) * DF + fbase + f2 * 2] = v;
    }
}

// ---------------------------------------------------------------------------
// Kernel 3: down fp16 GEMM, split-K=2 -> g_part.  CTA: 128 m x 128 s, BK=64.
// grid (4, 16, 2) = 128 CTAs -> single wave.  (R9 config)
// SMEM: 3 stages x (Ad|Bm = 36864 B) = 110592 B.
// ---------------------------------------------------------------------------
#define K3_STG (2 * TILE_H)
#define K3_SMEM (3 * K3_STG)

__global__ __launch_bounds__(256, 1) void k_gemm_down()
{
    extern __shared__ char smemc[];
    const uint32_t su = smem_u32(smemc);
    const int tid = threadIdx.x, wid = tid >> 5, lane = tid & 31;
    const int g = lane >> 2, tg = lane & 3;
    const int warp_m = wid & 3, warp_n = wid >> 2;
    const int sb = blockIdx.x * 128, mbase = blockIdx.y * 128;
    const int kbase = blockIdx.z * 4096;

    const uint32_t rA = a_off(lane, warp_m * 32);
    const uint32_t rB = b_off(lane, warp_n * 64);

    float acc[2][8][4];
    #pragma unroll
    for (int mt = 0; mt < 2; mt++)
        #pragma unroll
        for (int nt = 0; nt < 8; nt++)
            #pragma unroll
            for (int i = 0; i < 4; i++) acc[mt][nt][i] = 0.f;

    #pragma unroll
    for (int p = 0; p < 2; p++) {
        uint32_t b = su + p * K3_STG;
        load_tile64(b,          g_Wd,   mbase, DF, kbase + p * 64, tid);
        load_tile64(b + TILE_H, g_mlpT, sb,    DF, kbase + p * 64, tid);
        cp_commit();
    }

    int stg = 0;
    for (int i = 0; i < 64; i++) {
        if (i == 63) cp_wait0(); else cp_wait1();
        __syncthreads();
        if (i < 62) {
            int ns = stg + 2; if (ns >= 3) ns -= 3;
            uint32_t b = su + ns * K3_STG;
            int c0 = kbase + (i + 2) * 64;
            load_tile64(b,          g_Wd,   mbase, DF, c0, tid);
            load_tile64(b + TILE_H, g_mlpT, sb,    DF, c0, tid);
            cp_commit();
        }

        const uint32_t bAd = su + stg * K3_STG;
        const uint32_t bBm = bAd + TILE_H;

        #pragma unroll
        for (int ks = 0; ks < 4; ks++) {
            const uint32_t kb = ks * 32;
            uint32_t bq[4][4];
            #pragma unroll
            for (int p = 0; p < 4; p++)
                ldsm4(bq[p], bBm + rB + p * 2304 + kb);
            #pragma unroll
            for (int mt = 0; mt < 2; mt++) {
                uint32_t a[4];
                ldsm4(a, bAd + rA + mt * 2304 + kb);
                #pragma unroll
                for (int p = 0; p < 4; p++) {
                    mma16(acc[mt][2 * p],     a, &bq[p][0]);
                    mma16(acc[mt][2 * p + 1], a, &bq[p][2]);
                }
            }
        }
        if (++stg == 3) stg = 0;
    }
    __syncthreads();

    // epilogue: stage [m][s] fp32, coalesced float4 partial writes
    float* so = (float*)smemc;   // [128][132] = 67584 B < K3_SMEM
    #pragma unroll
    for (int mt = 0; mt < 2; mt++)
        #pragma unroll
        for (int nt = 0; nt < 8; nt++) {
            int r0 = warp_m * 32 + mt * 16 + g;
            int c0 = warp_n * 64 + nt * 8 + 2 * tg;
            #pragma unroll
            for (int i = 0; i < 4; i++)
                so[(r0 + (i >> 1) * 8) * 132 + c0 + (i & 1)] = acc[mt][nt][i];
        }
    __syncthreads();
    #pragma unroll
    for (int t = 0; t < 16; t++) {
        int idx = tid + t * 256;
        int m = idx >> 5, c4 = idx & 31;
        float4 v = *(const float4*)&so[m * 132 + c4 * 4];
        *(float4*)&g_part[(blockIdx.z * DM + mbase + m) * SL + sb + c4 * 4] = v;
    }
}

// ---------------------------------------------------------------------------
// Kernel 4: split-K reduce (K=2)
// ---------------------------------------------------------------------------
__global__ __launch_bounds__(256, 4) void k_reduce(float* __restrict__ out)
{
    int i = blockIdx.x * 256 + threadIdx.x;
    const float4* p = (const float4*)g_part;
    const int n4 = DM * SL / 4;
    float4 a = p[i], b = p[i + n4];
    float4 o;
    o.x = a.x + b.x; o.y = a.y + b.y; o.z = a.z + b.z; o.w = a.w + b.w;
    ((float4*)out)[i] = o;
}

// ---------------------------------------------------------------------------
extern "C" void kernel_launch(void* const* d_in, const int* in_sizes, int n_in,
                              void* d_out, int out_size)
{
    (void)in_sizes; (void)n_in; (void)out_size;
    const float* x  = (const float*)d_in[0];
    const float* Gs = (const float*)d_in[1];
    const float* GA = (const float*)d_in[2];
    const float* GB = (const float*)d_in[3];
    const float* Us = (const float*)d_in[4];
    const float* UA = (const float*)d_in[5];
    const float* UB = (const float*)d_in[6];
    const float* Ds = (const float*)d_in[7];
    const float* DA = (const float*)d_in[8];
    const float* DB = (const float*)d_in[9];
    float* out = (float*)d_out;

    cudaFuncSetAttribute(k_gemm_gateup, cudaFuncAttributeMaxDynamicSharedMemorySize, K2_SMEM);
    cudaFuncSetAttribute(k_gemm_down,   cudaFuncAttributeMaxDynamicSharedMemorySize, K3_SMEM);

    k_dequant<<<dim3(1024, 1, 3), 256>>>(Gs, GA, GB, Us, UA, UB, Ds, DA, DB);
    k_xt<<<dim3(DM / 32, SL / 32), 256>>>(x);

    k_gemm_gateup<<<dim3(SL / 128, DF / 128), 256, K2_SMEM>>>();
    k_gemm_down<<<dim3(SL / 128, DM / 128, 2), 256, K3_SMEM>>>();
    k_reduce<<<DM * SL / 4 / 256, 256>>>(out);
}

// round 12
// speedup vs baseline: 1.7650x; 1.0293x over previous
#include <cuda_runtime.h>
#include <cuda_fp16.h>
#include <cstdint>

#define DM 2048   // D_MODEL
#define DF 8192   // D_FF
#define RK 32     // RANK
#define SL 512    // S

// ---------------------------------------------------------------------------
// Global scratch
// ---------------------------------------------------------------------------
__device__ __half g_Wg[DF * DM];      // gate_eff fp16
__device__ __half g_Wu[DF * DM];      // up_eff fp16
__device__ __half g_Wd[DM * DF];      // down_eff fp16
__device__ __half g_xT[SL * DM];      // x transposed [s][c] fp16
__device__ __half g_mlpT[SL * DF];    // silu(g)*u transposed [s][ff] fp16
__device__ float  g_part[2 * DM * SL];// split-K=2 partials (fp32)

// ---------------------------------------------------------------------------
// Helpers
// ---------------------------------------------------------------------------
__device__ __forceinline__ float to_tf32(float x) {
    uint32_t u;
    asm("cvt.rna.tf32.f32 %0, %1;" : "=r"(u) : "f"(x));
    return __uint_as_float(u);
}
__device__ __forceinline__ uint32_t smem_u32(const void* p) {
    uint32_t a;
    asm("{ .reg .u64 t; cvta.to.shared.u64 t, %1; cvt.u32.u64 %0, t; }" : "=r"(a) : "l"(p));
    return a;
}
__device__ __forceinline__ void cp16(uint32_t dst, const void* src) {
    asm volatile("cp.async.cg.shared.global [%0], [%1], 16;" :: "r"(dst), "l"(src));
}
__device__ __forceinline__ void cp_commit() { asm volatile("cp.async.commit_group;"); }
__device__ __forceinline__ void cp_wait1()  { asm volatile("cp.async.wait_group 1;" ::: "memory"); }
__device__ __forceinline__ void cp_wait0()  { asm volatile("cp.async.wait_group 0;" ::: "memory"); }

// tf32 m16n8k8 (dequant scale GEMM)
__device__ __forceinline__ void mma8(float* c, const float* a, const float* b) {
    asm volatile(
        "mma.sync.aligned.m16n8k8.row.col.f32.tf32.tf32.f32 "
        "{%0,%1,%2,%3}, {%4,%5,%6,%7}, {%8,%9}, {%0,%1,%2,%3};"
        : "+f"(c[0]), "+f"(c[1]), "+f"(c[2]), "+f"(c[3])
        : "r"(__float_as_uint(a[0])), "r"(__float_as_uint(a[1])),
          "r"(__float_as_uint(a[2])), "r"(__float_as_uint(a[3])),
          "r"(__float_as_uint(b[0])), "r"(__float_as_uint(b[1])));
}
// fp16 m16n8k16 (main GEMMs), fp32 accum
__device__ __forceinline__ void mma16(float* c, const uint32_t* a, const uint32_t* b) {
    asm volatile(
        "mma.sync.aligned.m16n8k16.row.col.f32.f16.f16.f32 "
        "{%0,%1,%2,%3}, {%4,%5,%6,%7}, {%8,%9}, {%0,%1,%2,%3};"
        : "+f"(c[0]), "+f"(c[1]), "+f"(c[2]), "+f"(c[3])
        : "r"(a[0]), "r"(a[1]), "r"(a[2]), "r"(a[3]), "r"(b[0]), "r"(b[1]));
}
__device__ __forceinline__ void ldsm4(uint32_t* r, uint32_t addr) {
    asm volatile("ldmatrix.sync.aligned.m8n8.x4.shared.b16 {%0,%1,%2,%3}, [%4];"
                 : "=r"(r[0]), "=r"(r[1]), "=r"(r[2]), "=r"(r[3]) : "r"(addr));
}

// BK=64 tile: 128 rows x 64 k-halves padded to 72 (row stride 144 B, conflict-free ldmatrix)
#define PADH 72
#define TILE_H (128 * PADH * 2)    // 18432 B
#define ROW16 (16 * PADH * 2)      // 2304 B per 16-row step

// ---------------------------------------------------------------------------
// Kernel 1: merged dequant (R9-best staged version)
// ---------------------------------------------------------------------------
#define DQ_SMEM 67584

__global__ __launch_bounds__(256, 1) void k_dequant(
    const float* __restrict__ Gs, const float* __restrict__ GA, const float* __restrict__ GB,
    const float* __restrict__ Us, const float* __restrict__ UA, const float* __restrict__ UB,
    const float* __restrict__ Ds, const float* __restrict__ DA, const float* __restrict__ DB)
{
    extern __shared__ float dsm[];
    float* sA = dsm;                    // [128][36]
    float* sB = dsm + 128 * 36;         // [128][36] (B transposed)
    int tid = threadIdx.x, wid = tid >> 5, lane = tid & 31;
    int g = lane >> 2, tg = lane & 3;
    int wm = wid & 3, wn = wid >> 2;

    const float *Ws, *Aa, *Bb;
    __half* Wo;
    int cols, cb, fb;
    if (blockIdx.z == 0) {
        Ws = Gs; Aa = GA; Bb = GB; Wo = g_Wg; cols = DM;
        cb = (blockIdx.x & 15) * 128; fb = (blockIdx.x >> 4) * 128;
    } else if (blockIdx.z == 1) {
        Ws = Us; Aa = UA; Bb = UB; Wo = g_Wu; cols = DM;
        cb = (blockIdx.x & 15) * 128; fb = (blockIdx.x >> 4) * 128;
    } else {
        Ws = Ds; Aa = DA; Bb = DB; Wo = g_Wd; cols = DF;
        cb = (blockIdx.x & 63) * 128; fb = (blockIdx.x >> 6) * 128;
    }

    #pragma unroll
    for (int t = 0; t < 16; t++) {
        int idx = tid + t * 256;
        int r = idx >> 5, k = idx & 31;
        sA[r * 36 + k] = to_tf32(Aa[(fb + r) * RK + k]);
        int rr = idx >> 7, c = idx & 127;
        sB[c * 36 + rr] = to_tf32(Bb[rr * cols + cb + c]);
    }
    __syncthreads();

    float acc[2][8][4];
    #pragma unroll
    for (int mt = 0; mt < 2; mt++)
        #pragma unroll
        for (int nt = 0; nt < 8; nt++)
            #pragma unroll
            for (int i = 0; i < 4; i++) acc[mt][nt][i] = 0.f;

    #pragma unroll
    for (int ks = 0; ks < 4; ks++) {
        int k0 = ks * 8;
        float bq[8][2];
        #pragma unroll
        for (int nt = 0; nt < 8; nt++) {
            const float* bp = sB + (wn * 64 + nt * 8 + g) * 36 + k0 + tg;
            bq[nt][0] = bp[0]; bq[nt][1] = bp[4];
        }
        #pragma unroll
        for (int mt = 0; mt < 2; mt++) {
            const float* ap = sA + (wm * 32 + mt * 16 + g) * 36 + k0 + tg;
            float a[4] = { ap[0], ap[8 * 36], ap[4], ap[8 * 36 + 4] };
            #pragma unroll
            for (int nt = 0; nt < 8; nt++) mma8(acc[mt][nt], a, bq[nt]);
        }
    }
    __syncthreads();

    float* sS = dsm;   // [128][132]
    #pragma unroll
    for (int mt = 0; mt < 2; mt++)
        #pragma unroll
        for (int nt = 0; nt < 8; nt++) {
            int r0 = wm * 32 + mt * 16 + g;
            int c0 = wn * 64 + nt * 8 + 2 * tg;
            #pragma unroll
            for (int i = 0; i < 4; i++)
                sS[(r0 + (i >> 1) * 8) * 132 + c0 + (i & 1)] = acc[mt][nt][i];
        }
    __syncthreads();

    #pragma unroll
    for (int t = 0; t < 16; t++) {
        int idx = tid + t * 256;
        int r = idx >> 5, c4 = idx & 31;
        const float4 w = *(const float4*)&Ws[(fb + r) * cols + cb + c4 * 4];
        const float4 s = *(const float4*)&sS[r * 132 + c4 * 4];
        __half2 lo = __floats2half2_rn(w.x * s.x, w.y * s.y);
        __half2 hi = __floats2half2_rn(w.z * s.z, w.w * s.w);
        uint2 o = { *(uint32_t*)&lo, *(uint32_t*)&hi };
        *(uint2*)&Wo[(fb + r) * cols + cb + c4 * 4] = o;
    }
}

// ---------------------------------------------------------------------------
// x transpose -> fp16
// ---------------------------------------------------------------------------
__global__ __launch_bounds__(256, 4) void k_xt(const float* __restrict__ x)
{
    __shared__ float sm[32][33];
    int tid = threadIdx.x, tx = tid & 31, ty = tid >> 5;
    int cb = blockIdx.x * 32, sb = blockIdx.y * 32;
    #pragma unroll
    for (int i = 0; i < 4; i++)
        sm[ty + i * 8][tx] = x[(cb + ty + i * 8) * SL + sb + tx];
    __syncthreads();
    #pragma unroll
    for (int i = 0; i < 4; i++)
        g_xT[(sb + ty + i * 8) * DM + cb + tx] = __float2half_rn(sm[tx][ty + i * 8]);
}

// ---------------------------------------------------------------------------
// Stage loader: 128 rows x 64 k-halves -> [row][PADH]; 4 cp16 per thread
// ---------------------------------------------------------------------------
__device__ __forceinline__ void load_tile64(uint32_t dst, const __half* __restrict__ src,
                                            int row_base, int ld, int c0, int tid)
{
    #pragma unroll
    for (int t = 0; t < 4; t++) {
        int id = tid + t * 256;
        int r = id >> 3, cbk = id & 7;
        cp16(dst + (r * PADH + cbk * 8) * 2, src + (row_base + r) * ld + c0 + cbk * 8);
    }
}

// ldmatrix per-lane byte offsets
__device__ __forceinline__ uint32_t a_off(int lane, int row_base) {
    return (uint32_t)((row_base + (lane & 15)) * (PADH * 2) + ((lane >> 4) * 16));
}
__device__ __forceinline__ uint32_t b_off(int lane, int row_base) {
    return (uint32_t)((row_base + ((lane >> 4) * 8) + (lane & 7)) * (PADH * 2) +
                      (((lane >> 3) & 1) * 16));
}

// ---------------------------------------------------------------------------
// Kernel 2: gate+up fp16 GEMM + SwiGLU -> g_mlpT (fp16)
// CTA: 128 f x 128 s, BK=64, 32 iters, 3-stage cp.async pipeline,
// register fragment double-buffer across ks-steps.
// ---------------------------------------------------------------------------
#define K2_STG (3 * TILE_H)
#define K2_SMEM (3 * K2_STG)

__global__ __launch_bounds__(256, 1) void k_gemm_gateup()
{
    extern __shared__ char smemc[];
    __half* smh = (__half*)smemc;
    const uint32_t su = smem_u32(smemc);
    const int tid = threadIdx.x, wid = tid >> 5, lane = tid & 31;
    const int g = lane >> 2, tg = lane & 3;
    const int warp_m = wid & 3, warp_n = wid >> 2;
    const int sb = blockIdx.x * 128, fbase = blockIdx.y * 128;

    const uint32_t rA = a_off(lane, warp_m * 32);
    const uint32_t rB = b_off(lane, warp_n * 64);

    float accg[2][8][4], accu[2][8][4];
    #pragma unroll
    for (int mt = 0; mt < 2; mt++)
        #pragma unroll
        for (int nt = 0; nt < 8; nt++)
            #pragma unroll
            for (int i = 0; i < 4; i++) { accg[mt][nt][i] = 0.f; accu[mt][nt][i] = 0.f; }

    #pragma unroll
    for (int p = 0; p < 2; p++) {
        uint32_t b = su + p * K2_STG;
        load_tile64(b,              g_Wg, fbase, DM, p * 64, tid);
        load_tile64(b + TILE_H,     g_Wu, fbase, DM, p * 64, tid);
        load_tile64(b + 2 * TILE_H, g_xT, sb,    DM, p * 64, tid);
        cp_commit();
    }

    // fragment double-buffers
    uint32_t fbq[2][16], fag[2][8], fau[2][8];

    int stg = 0;
    for (int i = 0; i < 32; i++) {
        if (i == 31) cp_wait0(); else cp_wait1();
        __syncthreads();
        if (i < 30) {
            int ns = stg + 2; if (ns >= 3) ns -= 3;
            uint32_t b = su + ns * K2_STG;
            int c0 = (i + 2) * 64;
            load_tile64(b,              g_Wg, fbase, DM, c0, tid);
            load_tile64(b + TILE_H,     g_Wu, fbase, DM, c0, tid);
            load_tile64(b + 2 * TILE_H, g_xT, sb,    DM, c0, tid);
            cp_commit();
        }

        const uint32_t bAg = su + stg * K2_STG;
        const uint32_t bAu = bAg + TILE_H;
        const uint32_t bBx = bAg + 2 * TILE_H;

        // prime ks=0 fragments
        #pragma unroll
        for (int p = 0; p < 4; p++) ldsm4(&fbq[0][p * 4], bBx + rB + p * ROW16);
        ldsm4(&fag[0][0], bAg + rA);
        ldsm4(&fag[0][4], bAg + rA + ROW16);
        ldsm4(&fau[0][0], bAu + rA);
        ldsm4(&fau[0][4], bAu + rA + ROW16);

        #pragma unroll
        for (int ks = 0; ks < 4; ks++) {
            const int cur = ks & 1, nxt = cur ^ 1;
            if (ks < 3) {
                const uint32_t kb = (ks + 1) * 32;
                #pragma unroll
                for (int p = 0; p < 4; p++) ldsm4(&fbq[nxt][p * 4], bBx + rB + p * ROW16 + kb);
                ldsm4(&fag[nxt][0], bAg + rA + kb);
                ldsm4(&fag[nxt][4], bAg + rA + ROW16 + kb);
                ldsm4(&fau[nxt][0], bAu + rA + kb);
                ldsm4(&fau[nxt][4], bAu + rA + ROW16 + kb);
            }
            #pragma unroll
            for (int mt = 0; mt < 2; mt++)
                #pragma unroll
                for (int p = 0; p < 4; p++) {
                    mma16(accg[mt][2 * p],     &fag[cur][mt * 4], &fbq[cur][p * 4]);
                    mma16(accg[mt][2 * p + 1], &fag[cur][mt * 4], &fbq[cur][p * 4 + 2]);
                    mma16(accu[mt][2 * p],     &fau[cur][mt * 4], &fbq[cur][p * 4]);
                    mma16(accu[mt][2 * p + 1], &fau[cur][mt * 4], &fbq[cur][p * 4 + 2]);
                }
        }
        if (++stg == 3) stg = 0;
    }
    __syncthreads();

    // epilogue: SwiGLU, transpose via smem (half), coalesced write
    __half* so = smh;   // [s 128][f pad 136] halves = 34816 B
    #pragma unroll
    for (int mt = 0; mt < 2; mt++)
        #pragma unroll
        for (int nt = 0; nt < 8; nt++) {
            int r0 = warp_m * 32 + mt * 16 + g;
            int c0 = warp_n * 64 + nt * 8 + 2 * tg;
            #pragma unroll
            for (int i = 0; i < 4; i++) {
                float gg = accg[mt][nt][i], uu = accu[mt][nt][i];
                float m = (gg / (1.f + __expf(-gg))) * uu;
                so[(c0 + (i & 1)) * 136 + r0 + (i >> 1) * 8] = __float2half_rn(m);
            }
        }
    __syncthreads();
    #pragma unroll
    for (int t = 0; t < 32; t++) {
        int idx = tid + t * 256;
        int s = idx >> 6, f2 = idx & 63;
        uint32_t v = *(const uint32_t*)&so[s * 136 + f2 * 2];
        *(uint32_t*)&g_mlpT[(sb + s) * DF + fbase + f2 * 2] = v;
    }
}

// ---------------------------------------------------------------------------
// Kernel 3: down fp16 GEMM, split-K=2 -> g_part.  CTA: 128 m x 128 s, BK=64.
// grid (4, 16, 2) = 128 CTAs.  Register fragment double-buffer.
// ---------------------------------------------------------------------------
#define K3_STG (2 * TILE_H)
#define K3_SMEM (3 * K3_STG)

__global__ __launch_bounds__(256, 1) void k_gemm_down()
{
    extern __shared__ char smemc[];
    const uint32_t su = smem_u32(smemc);
    const int tid = threadIdx.x, wid = tid >> 5, lane = tid & 31;
    const int g = lane >> 2, tg = lane & 3;
    const int warp_m = wid & 3, warp_n = wid >> 2;
    const int sb = blockIdx.x * 128, mbase = blockIdx.y * 128;
    const int kbase = blockIdx.z * 4096;

    const uint32_t rA = a_off(lane, warp_m * 32);
    const uint32_t rB = b_off(lane, warp_n * 64);

    float acc[2][8][4];
    #pragma unroll
    for (int mt = 0; mt < 2; mt++)
        #pragma unroll
        for (int nt = 0; nt < 8; nt++)
            #pragma unroll
            for (int i = 0; i < 4; i++) acc[mt][nt][i] = 0.f;

    #pragma unroll
    for (int p = 0; p < 2; p++) {
        uint32_t b = su + p * K3_STG;
        load_tile64(b,          g_Wd,   mbase, DF, kbase + p * 64, tid);
        load_tile64(b + TILE_H, g_mlpT, sb,    DF, kbase + p * 64, tid);
        cp_commit();
    }

    uint32_t fbq[2][16], fa[2][8];

    int stg = 0;
    for (int i = 0; i < 64; i++) {
        if (i == 63) cp_wait0(); else cp_wait1();
        __syncthreads();
        if (i < 62) {
            int ns = stg + 2; if (ns >= 3) ns -= 3;
            uint32_t b = su + ns * K3_STG;
            int c0 = kbase + (i + 2) * 64;
            load_tile64(b,          g_Wd,   mbase, DF, c0, tid);
            load_tile64(b + TILE_H, g_mlpT, sb,    DF, c0, tid);
            cp_commit();
        }

        const uint32_t bAd = su + stg * K3_STG;
        const uint32_t bBm = bAd + TILE_H;

        #pragma unroll
        for (int p = 0; p < 4; p++) ldsm4(&fbq[0][p * 4], bBm + rB + p * ROW16);
        ldsm4(&fa[0][0], bAd + rA);
        ldsm4(&fa[0][4], bAd + rA + ROW16);

        #pragma unroll
        for (int ks = 0; ks < 4; ks++) {
            const int cur = ks & 1, nxt = cur ^ 1;
            if (ks < 3) {
                const uint32_t kb = (ks + 1) * 32;
                #pragma unroll
                for (int p = 0; p < 4; p++) ldsm4(&fbq[nxt][p * 4], bBm + rB + p * ROW16 + kb);
                ldsm4(&fa[nxt][0], bAd + rA + kb);
                ldsm4(&fa[nxt][4], bAd + rA + ROW16 + kb);
            }
            #pragma unroll
            for (int mt = 0; mt < 2; mt++)
                #pragma unroll
                for (int p = 0; p < 4; p++) {
                    mma16(acc[mt][2 * p],     &fa[cur][mt * 4], &fbq[cur][p * 4]);
                    mma16(acc[mt][2 * p + 1], &fa[cur][mt * 4], &fbq[cur][p * 4 + 2]);
                }
        }
        if (++stg == 3) stg = 0;
    }
    __syncthreads();

    // epilogue: stage [m][s] fp32, coalesced float4 partial writes
    float* so = (float*)smemc;   // [128][132] = 67584 B < K3_SMEM
    #pragma unroll
    for (int mt = 0; mt < 2; mt++)
        #pragma unroll
        for (int nt = 0; nt < 8; nt++) {
            int r0 = warp_m * 32 + mt * 16 + g;
            int c0 = warp_n * 64 + nt * 8 + 2 * tg;
            #pragma unroll
            for (int i = 0; i < 4; i++)
                so[(r0 + (i >> 1) * 8) * 132 + c0 + (i & 1)] = acc[mt][nt][i];
        }
    __syncthreads();
    #pragma unroll
    for (int t = 0; t < 16; t++) {
        int idx = tid + t * 256;
        int m = idx >> 5, c4 = idx & 31;
        float4 v = *(const float4*)&so[m * 132 + c4 * 4];
        *(float4*)&g_part[(blockIdx.z * DM + mbase + m) * SL + sb + c4 * 4] = v;
    }
}

// ---------------------------------------------------------------------------
// Kernel 4: split-K reduce (K=2)
// ---------------------------------------------------------------------------
__global__ __launch_bounds__(256, 4) void k_reduce(float* __restrict__ out)
{
    int i = blockIdx.x * 256 + threadIdx.x;
    const float4* p = (const float4*)g_part;
    const int n4 = DM * SL / 4;
    float4 a = p[i], b = p[i + n4];
    float4 o;
    o.x = a.x + b.x; o.y = a.y + b.y; o.z = a.z + b.z; o.w = a.w + b.w;
    ((float4*)out)[i] = o;
}

// ---------------------------------------------------------------------------
extern "C" void kernel_launch(void* const* d_in, const int* in_sizes, int n_in,
                              void* d_out, int out_size)
{
    (void)in_sizes; (void)n_in; (void)out_size;
    const float* x  = (const float*)d_in[0];
    const float* Gs = (const float*)d_in[1];
    const float* GA = (const float*)d_in[2];
    const float* GB = (const float*)d_in[3];
    const float* Us = (const float*)d_in[4];
    const float* UA = (const float*)d_in[5];
    const float* UB = (const float*)d_in[6];
    const float* Ds = (const float*)d_in[7];
    const float* DA = (const float*)d_in[8];
    const float* DB = (const float*)d_in[9];
    float* out = (float*)d_out;

    cudaFuncSetAttribute(k_dequant,     cudaFuncAttributeMaxDynamicSharedMemorySize, DQ_SMEM);
    cudaFuncSetAttribute(k_gemm_gateup, cudaFuncAttributeMaxDynamicSharedMemorySize, K2_SMEM);
    cudaFuncSetAttribute(k_gemm_down,   cudaFuncAttributeMaxDynamicSharedMemorySize, K3_SMEM);

    k_dequant<<<dim3(1024, 1, 3), 256, DQ_SMEM>>>(Gs, GA, GB, Us, UA, UB, Ds, DA, DB);
    k_xt<<<dim3(DM / 32, SL / 32), 256>>>(x);

    k_gemm_gateup<<<dim3(SL / 128, DF / 128), 256, K2_SMEM>>>();
    k_gemm_down<<<dim3(SL / 128, DM / 128, 2), 256, K3_SMEM>>>();
    k_reduce<<<DM * SL / 4 / 256, 256>>>(out);
}

// round 15
// speedup vs baseline: 1.8554x; 1.0512x over previous
#include <cuda_runtime.h>
#include <cuda_fp16.h>
#include <cstdint>

#define DM 2048   // D_MODEL
#define DF 8192   // D_FF
#define RK 32     // RANK
#define SL 512    // S

// ---------------------------------------------------------------------------
// Global scratch
// ---------------------------------------------------------------------------
__device__ __half g_Wg[DF * DM];      // gate_eff fp16
__device__ __half g_Wu[DF * DM];      // up_eff fp16
__device__ __half g_Wd[DM * DF];      // down_eff fp16
__device__ __half g_xT[SL * DM];      // x transposed [s][c] fp16
__device__ __half g_mlpT[SL * DF];    // silu(g)*u transposed [s][ff] fp16
__device__ float  g_part[2 * DM * SL];// split-K=2 partials (fp32)

// ---------------------------------------------------------------------------
// Helpers
// ---------------------------------------------------------------------------
__device__ __forceinline__ float to_tf32(float x) {
    uint32_t u;
    asm("cvt.rna.tf32.f32 %0, %1;" : "=r"(u) : "f"(x));
    return __uint_as_float(u);
}
__device__ __forceinline__ uint32_t smem_u32(const void* p) {
    uint32_t a;
    asm("{ .reg .u64 t; cvta.to.shared.u64 t, %1; cvt.u32.u64 %0, t; }" : "=r"(a) : "l"(p));
    return a;
}
__device__ __forceinline__ void cp16(uint32_t dst, const void* src) {
    asm volatile("cp.async.cg.shared.global [%0], [%1], 16;" :: "r"(dst), "l"(src));
}
__device__ __forceinline__ void cp_commit() { asm volatile("cp.async.commit_group;"); }
__device__ __forceinline__ void cp_wait1()  { asm volatile("cp.async.wait_group 1;" ::: "memory"); }
__device__ __forceinline__ void cp_wait0()  { asm volatile("cp.async.wait_group 0;" ::: "memory"); }

// tf32 m16n8k8 (dequant scale GEMM)
__device__ __forceinline__ void mma8(float* c, const float* a, const float* b) {
    asm volatile(
        "mma.sync.aligned.m16n8k8.row.col.f32.tf32.tf32.f32 "
        "{%0,%1,%2,%3}, {%4,%5,%6,%7}, {%8,%9}, {%0,%1,%2,%3};"
        : "+f"(c[0]), "+f"(c[1]), "+f"(c[2]), "+f"(c[3])
        : "r"(__float_as_uint(a[0])), "r"(__float_as_uint(a[1])),
          "r"(__float_as_uint(a[2])), "r"(__float_as_uint(a[3])),
          "r"(__float_as_uint(b[0])), "r"(__float_as_uint(b[1])));
}
// fp16 m16n8k16 (main GEMMs), fp32 accum
__device__ __forceinline__ void mma16(float* c, const uint32_t* a, const uint32_t* b) {
    asm volatile(
        "mma.sync.aligned.m16n8k16.row.col.f32.f16.f16.f32 "
        "{%0,%1,%2,%3}, {%4,%5,%6,%7}, {%8,%9}, {%0,%1,%2,%3};"
        : "+f"(c[0]), "+f"(c[1]), "+f"(c[2]), "+f"(c[3])
        : "r"(a[0]), "r"(a[1]), "r"(a[2]), "r"(a[3]), "r"(b[0]), "r"(b[1]));
}
__device__ __forceinline__ void ldsm4(uint32_t* r, uint32_t addr) {
    asm volatile("ldmatrix.sync.aligned.m8n8.x4.shared.b16 {%0,%1,%2,%3}, [%4];"
                 : "=r"(r[0]), "=r"(r[1]), "=r"(r[2]), "=r"(r[3]) : "r"(addr));
}

// BK=64 tile: 128 rows x 64 k-halves padded to 72 (row stride 144 B, conflict-free ldmatrix)
#define PADH 72
#define TILE_H (128 * PADH * 2)    // 18432 B
#define ROW16 (16 * PADH * 2)      // 2304 B per 16-row step

// ---------------------------------------------------------------------------
// Kernel 1: merged dequant for 3 matrices (z=0..2), standalone (R12 structure).
// MMA scale tile, then TWO 64-col half-passes staged through a 34816 B buffer
// aliasing sA/sB -> static smem 36864 B, occ 2 (regs <= 128).
// ---------------------------------------------------------------------------
__global__ __launch_bounds__(256, 2) void k_dequant(
    const float* __restrict__ Gs, const float* __restrict__ GA, const float* __restrict__ GB,
    const float* __restrict__ Us, const float* __restrict__ UA, const float* __restrict__ UB,
    const float* __restrict__ Ds, const float* __restrict__ DA, const float* __restrict__ DB)
{
    __shared__ float dsm[128 * 36 * 2];   // 36864 B
    float* sA = dsm;                      // [128][36]
    float* sB = dsm + 128 * 36;           // [128][36] (B transposed)
    int tid = threadIdx.x, wid = tid >> 5, lane = tid & 31;
    int g = lane >> 2, tg = lane & 3;
    int wm = wid & 3, wn = wid >> 2;

    const float *Ws, *Aa, *Bb;
    __half* Wo;
    int cols, cb, fb;
    if (blockIdx.z == 0) {
        Ws = Gs; Aa = GA; Bb = GB; Wo = g_Wg; cols = DM;
        cb = (blockIdx.x & 15) * 128; fb = (blockIdx.x >> 4) * 128;
    } else if (blockIdx.z == 1) {
        Ws = Us; Aa = UA; Bb = UB; Wo = g_Wu; cols = DM;
        cb = (blockIdx.x & 15) * 128; fb = (blockIdx.x >> 4) * 128;
    } else {
        Ws = Ds; Aa = DA; Bb = DB; Wo = g_Wd; cols = DF;
        cb = (blockIdx.x & 63) * 128; fb = (blockIdx.x >> 6) * 128;
    }

    #pragma unroll
    for (int t = 0; t < 16; t++) {
        int idx = tid + t * 256;
        int r = idx >> 5, k = idx & 31;
        sA[r * 36 + k] = to_tf32(Aa[(fb + r) * RK + k]);
        int rr = idx >> 7, c = idx & 127;
        sB[c * 36 + rr] = to_tf32(Bb[rr * cols + cb + c]);
    }
    __syncthreads();

    float acc[2][8][4];
    #pragma unroll
    for (int mt = 0; mt < 2; mt++)
        #pragma unroll
        for (int nt = 0; nt < 8; nt++)
            #pragma unroll
            for (int i = 0; i < 4; i++) acc[mt][nt][i] = 0.f;

    #pragma unroll
    for (int ks = 0; ks < 4; ks++) {
        int k0 = ks * 8;
        float bq[8][2];
        #pragma unroll
        for (int nt = 0; nt < 8; nt++) {
            const float* bp = sB + (wn * 64 + nt * 8 + g) * 36 + k0 + tg;
            bq[nt][0] = bp[0]; bq[nt][1] = bp[4];
        }
        #pragma unroll
        for (int mt = 0; mt < 2; mt++) {
            const float* ap = sA + (wm * 32 + mt * 16 + g) * 36 + k0 + tg;
            float a[4] = { ap[0], ap[8 * 36], ap[4], ap[8 * 36 + 4] };
            #pragma unroll
            for (int nt = 0; nt < 8; nt++) mma8(acc[mt][nt], a, bq[nt]);
        }
    }
    __syncthreads();   // sA/sB reads complete; alias staging buffer over them

    float* sS = dsm;   // [128][68] fp32 = 34816 B
    #pragma unroll
    for (int h = 0; h < 2; h++) {
        if (wn == h) {
            #pragma unroll
            for (int mt = 0; mt < 2; mt++)
                #pragma unroll
                for (int nt = 0; nt < 8; nt++) {
                    int r0 = wm * 32 + mt * 16 + g;
                    int c0 = nt * 8 + 2 * tg;
                    #pragma unroll
                    for (int i = 0; i < 4; i++)
                        sS[(r0 + (i >> 1) * 8) * 68 + c0 + (i & 1)] = acc[mt][nt][i];
                }
        }
        __syncthreads();
        #pragma unroll
        for (int t = 0; t < 8; t++) {
            int idx = tid + t * 256;        // 0..2047 float4 groups
            int r = idx >> 4, c4 = idx & 15;
            const float4 w = *(const float4*)&Ws[(fb + r) * cols + cb + h * 64 + c4 * 4];
            const float4 s = *(const float4*)&sS[r * 68 + c4 * 4];
            __half2 lo = __floats2half2_rn(w.x * s.x, w.y * s.y);
            __half2 hi = __floats2half2_rn(w.z * s.z, w.w * s.w);
            uint2 o = { *(uint32_t*)&lo, *(uint32_t*)&hi };
            *(uint2*)&Wo[(fb + r) * cols + cb + h * 64 + c4 * 4] = o;
        }
        __syncthreads();
    }
}

// ---------------------------------------------------------------------------
// x transpose -> fp16  (R12 config, unchanged)
// ---------------------------------------------------------------------------
__global__ __launch_bounds__(256, 4) void k_xt(const float* __restrict__ x)
{
    __shared__ float sm[32][33];
    int tid = threadIdx.x, tx = tid & 31, ty = tid >> 5;
    int cb = blockIdx.x * 32, sb = blockIdx.y * 32;
    #pragma unroll
    for (int i = 0; i < 4; i++)
        sm[ty + i * 8][tx] = x[(cb + ty + i * 8) * SL + sb + tx];
    __syncthreads();
    #pragma unroll
    for (int i = 0; i < 4; i++)
        g_xT[(sb + ty + i * 8) * DM + cb + tx] = __float2half_rn(sm[tx][ty + i * 8]);
}

// ---------------------------------------------------------------------------
// Stage loader: 128 rows x 64 k-halves -> [row][PADH]; 4 cp16 per thread
// ---------------------------------------------------------------------------
__device__ __forceinline__ void load_tile64(uint32_t dst, const __half* __restrict__ src,
                                            int row_base, int ld, int c0, int tid)
{
    #pragma unroll
    for (int t = 0; t < 4; t++) {
        int id = tid + t * 256;
        int r = id >> 3, cbk = id & 7;
        cp16(dst + (r * PADH + cbk * 8) * 2, src + (row_base + r) * ld + c0 + cbk * 8);
    }
}

// ldmatrix per-lane byte offsets
__device__ __forceinline__ uint32_t a_off(int lane, int row_base) {
    return (uint32_t)((row_base + (lane & 15)) * (PADH * 2) + ((lane >> 4) * 16));
}
__device__ __forceinline__ uint32_t b_off(int lane, int row_base) {
    return (uint32_t)((row_base + ((lane >> 4) * 8) + (lane & 7)) * (PADH * 2) +
                      (((lane >> 3) & 1) * 16));
}

// ---------------------------------------------------------------------------
// Kernel 2: gate+up fp16 GEMM + SwiGLU -> g_mlpT (fp16)   (R12 config)
// ---------------------------------------------------------------------------
#define K2_STG (3 * TILE_H)
#define K2_SMEM (3 * K2_STG)

__global__ __launch_bounds__(256, 1) void k_gemm_gateup()
{
    extern __shared__ char smemc[];
    __half* smh = (__half*)smemc;
    const uint32_t su = smem_u32(smemc);
    const int tid = threadIdx.x, wid = tid >> 5, lane = tid & 31;
    const int g = lane >> 2, tg = lane & 3;
    const int warp_m = wid & 3, warp_n = wid >> 2;
    const int sb = blockIdx.x * 128, fbase = blockIdx.y * 128;

    const uint32_t rA = a_off(lane, warp_m * 32);
    const uint32_t rB = b_off(lane, warp_n * 64);

    float accg[2][8][4], accu[2][8][4];
    #pragma unroll
    for (int mt = 0; mt < 2; mt++)
        #pragma unroll
        for (int nt = 0; nt < 8; nt++)
            #pragma unroll
            for (int i = 0; i < 4; i++) { accg[mt][nt][i] = 0.f; accu[mt][nt][i] = 0.f; }

    #pragma unroll
    for (int p = 0; p < 2; p++) {
        uint32_t b = su + p * K2_STG;
        load_tile64(b,              g_Wg, fbase, DM, p * 64, tid);
        load_tile64(b + TILE_H,     g_Wu, fbase, DM, p * 64, tid);
        load_tile64(b + 2 * TILE_H, g_xT, sb,    DM, p * 64, tid);
        cp_commit();
    }

    uint32_t fbq[2][16], fag[2][8], fau[2][8];

    int stg = 0;
    for (int i = 0; i < 32; i++) {
        if (i == 31) cp_wait0(); else cp_wait1();
        __syncthreads();
        if (i < 30) {
            int ns = stg + 2; if (ns >= 3) ns -= 3;
            uint32_t b = su + ns * K2_STG;
            int c0 = (i + 2) * 64;
            load_tile64(b,              g_Wg, fbase, DM, c0, tid);
            load_tile64(b + TILE_H,     g_Wu, fbase, DM, c0, tid);
            load_tile64(b + 2 * TILE_H, g_xT, sb,    DM, c0, tid);
            cp_commit();
        }

        const uint32_t bAg = su + stg * K2_STG;
        const uint32_t bAu = bAg + TILE_H;
        const uint32_t bBx = bAg + 2 * TILE_H;

        #pragma unroll
        for (int p = 0; p < 4; p++) ldsm4(&fbq[0][p * 4], bBx + rB + p * ROW16);
        ldsm4(&fag[0][0], bAg + rA);
        ldsm4(&fag[0][4], bAg + rA + ROW16);
        ldsm4(&fau[0][0], bAu + rA);
        ldsm4(&fau[0][4], bAu + rA + ROW16);

        #pragma unroll
        for (int ks = 0; ks < 4; ks++) {
            const int cur = ks & 1, nxt = cur ^ 1;
            if (ks < 3) {
                const uint32_t kb = (ks + 1) * 32;
                #pragma unroll
                for (int p = 0; p < 4; p++) ldsm4(&fbq[nxt][p * 4], bBx + rB + p * ROW16 + kb);
                ldsm4(&fag[nxt][0], bAg + rA + kb);
                ldsm4(&fag[nxt][4], bAg + rA + ROW16 + kb);
                ldsm4(&fau[nxt][0], bAu + rA + kb);
                ldsm4(&fau[nxt][4], bAu + rA + ROW16 + kb);
            }
            #pragma unroll
            for (int mt = 0; mt < 2; mt++)
                #pragma unroll
                for (int p = 0; p < 4; p++) {
                    mma16(accg[mt][2 * p],     &fag[cur][mt * 4], &fbq[cur][p * 4]);
                    mma16(accg[mt][2 * p + 1], &fag[cur][mt * 4], &fbq[cur][p * 4 + 2]);
                    mma16(accu[mt][2 * p],     &fau[cur][mt * 4], &fbq[cur][p * 4]);
                    mma16(accu[mt][2 * p + 1], &fau[cur][mt * 4], &fbq[cur][p * 4 + 2]);
                }
        }
        if (++stg == 3) stg = 0;
    }
    __syncthreads();

    __half* so = smh;   // [s 128][f pad 136]
    #pragma unroll
    for (int mt = 0; mt < 2; mt++)
        #pragma unroll
        for (int nt = 0; nt < 8; nt++) {
            int r0 = warp_m * 32 + mt * 16 + g;
            int c0 = warp_n * 64 + nt * 8 + 2 * tg;
            #pragma unroll
            for (int i = 0; i < 4; i++) {
                float gg = accg[mt][nt][i], uu = accu[mt][nt][i];
                float m = (gg / (1.f + __expf(-gg))) * uu;
                so[(c0 + (i & 1)) * 136 + r0 + (i >> 1) * 8] = __float2half_rn(m);
            }
        }
    __syncthreads();
    #pragma unroll
    for (int t = 0; t < 32; t++) {
        int idx = tid + t * 256;
        int s = idx >> 6, f2 = idx & 63;
        uint32_t v = *(const uint32_t*)&so[s * 136 + f2 * 2];
        *(uint32_t*)&g_mlpT[(sb + s) * DF + fbase + f2 * 2] = v;
    }
}

// ---------------------------------------------------------------------------
// Kernel 3: down fp16 GEMM, split-K=2 -> g_part   (R12 config)
// ---------------------------------------------------------------------------
#define K3_STG (2 * TILE_H)
#define K3_SMEM (3 * K3_STG)

__global__ __launch_bounds__(256, 1) void k_gemm_down()
{
    extern __shared__ char smemc[];
    const uint32_t su = smem_u32(smemc);
    const int tid = threadIdx.x, wid = tid >> 5, lane = tid & 31;
    const int g = lane >> 2, tg = lane & 3;
    const int warp_m = wid & 3, warp_n = wid >> 2;
    const int sb = blockIdx.x * 128, mbase = blockIdx.y * 128;
    const int kbase = blockIdx.z * 4096;

    const uint32_t rA = a_off(lane, warp_m * 32);
    const uint32_t rB = b_off(lane, warp_n * 64);

    float acc[2][8][4];
    #pragma unroll
    for (int mt = 0; mt < 2; mt++)
        #pragma unroll
        for (int nt = 0; nt < 8; nt++)
            #pragma unroll
            for (int i = 0; i < 4; i++) acc[mt][nt][i] = 0.f;

    #pragma unroll
    for (int p = 0; p < 2; p++) {
        uint32_t b = su + p * K3_STG;
        load_tile64(b,          g_Wd,   mbase, DF, kbase + p * 64, tid);
        load_tile64(b + TILE_H, g_mlpT, sb,    DF, kbase + p * 64, tid);
        cp_commit();
    }

    uint32_t fbq[2][16], fa[2][8];

    int stg = 0;
    for (int i = 0; i < 64; i++) {
        if (i == 63) cp_wait0(); else cp_wait1();
        __syncthreads();
        if (i < 62) {
            int ns = stg + 2; if (ns >= 3) ns -= 3;
            uint32_t b = su + ns * K3_STG;
            int c0 = kbase + (i + 2) * 64;
            load_tile64(b,          g_Wd,   mbase, DF, c0, tid);
            load_tile64(b + TILE_H, g_mlpT, sb,    DF, c0, tid);
            cp_commit();
        }

        const uint32_t bAd = su + stg * K3_STG;
        const uint32_t bBm = bAd + TILE_H;

        #pragma unroll
        for (int p = 0; p < 4; p++) ldsm4(&fbq[0][p * 4], bBm + rB + p * ROW16);
        ldsm4(&fa[0][0], bAd + rA);
        ldsm4(&fa[0][4], bAd + rA + ROW16);

        #pragma unroll
        for (int ks = 0; ks < 4; ks++) {
            const int cur = ks & 1, nxt = cur ^ 1;
            if (ks < 3) {
                const uint32_t kb = (ks + 1) * 32;
                #pragma unroll
                for (int p = 0; p < 4; p++) ldsm4(&fbq[nxt][p * 4], bBm + rB + p * ROW16 + kb);
                ldsm4(&fa[nxt][0], bAd + rA + kb);
                ldsm4(&fa[nxt][4], bAd + rA + ROW16 + kb);
            }
            #pragma unroll
            for (int mt = 0; mt < 2; mt++)
                #pragma unroll
                for (int p = 0; p < 4; p++) {
                    mma16(acc[mt][2 * p],     &fa[cur][mt * 4], &fbq[cur][p * 4]);
                    mma16(acc[mt][2 * p + 1], &fa[cur][mt * 4], &fbq[cur][p * 4 + 2]);
                }
        }
        if (++stg == 3) stg = 0;
    }
    __syncthreads();

    float* so = (float*)smemc;   // [128][132]
    #pragma unroll
    for (int mt = 0; mt < 2; mt++)
        #pragma unroll
        for (int nt = 0; nt < 8; nt++) {
            int r0 = warp_m * 32 + mt * 16 + g;
            int c0 = warp_n * 64 + nt * 8 + 2 * tg;
            #pragma unroll
            for (int i = 0; i < 4; i++)
                so[(r0 + (i >> 1) * 8) * 132 + c0 + (i & 1)] = acc[mt][nt][i];
        }
    __syncthreads();
    #pragma unroll
    for (int t = 0; t < 16; t++) {
        int idx = tid + t * 256;
        int m = idx >> 5, c4 = idx & 31;
        float4 v = *(const float4*)&so[m * 132 + c4 * 4];
        *(float4*)&g_part[(blockIdx.z * DM + mbase + m) * SL + sb + c4 * 4] = v;
    }
}

// ---------------------------------------------------------------------------
// Kernel 4: split-K reduce (K=2)
// ---------------------------------------------------------------------------
__global__ __launch_bounds__(256, 4) void k_reduce(float* __restrict__ out)
{
    int i = blockIdx.x * 256 + threadIdx.x;
    const float4* p = (const float4*)g_part;
    const int n4 = DM * SL / 4;
    float4 a = p[i], b = p[i + n4];
    float4 o;
    o.x = a.x + b.x; o.y = a.y + b.y; o.z = a.z + b.z; o.w = a.w + b.w;
    ((float4*)out)[i] = o;
}

// ---------------------------------------------------------------------------
extern "C" void kernel_launch(void* const* d_in, const int* in_sizes, int n_in,
                              void* d_out, int out_size)
{
    (void)in_sizes; (void)n_in; (void)out_size;
    const float* x  = (const float*)d_in[0];
    const float* Gs = (const float*)d_in[1];
    const float* GA = (const float*)d_in[2];
    const float* GB = (const float*)d_in[3];
    const float* Us = (const float*)d_in[4];
    const float* UA = (const float*)d_in[5];
    const float* UB = (const float*)d_in[6];
    const float* Ds = (const float*)d_in[7];
    const float* DA = (const float*)d_in[8];
    const float* DB = (const float*)d_in[9];
    float* out = (float*)d_out;

    cudaFuncSetAttribute(k_gemm_gateup, cudaFuncAttributeMaxDynamicSharedMemorySize, K2_SMEM);
    cudaFuncSetAttribute(k_gemm_down,   cudaFuncAttributeMaxDynamicSharedMemorySize, K3_SMEM);

    k_dequant<<<dim3(1024, 1, 3), 256>>>(Gs, GA, GB, Us, UA, UB, Ds, DA, DB);
    k_xt<<<dim3(DM / 32, SL / 32), 256>>>(x);

    k_gemm_gateup<<<dim3(SL / 128, DF / 128), 256, K2_SMEM>>>();
    k_gemm_down<<<dim3(SL / 128, DM / 128, 2), 256, K3_SMEM>>>();
    k_reduce<<<DM * SL / 4 / 256, 256>>>(out);
}